// round 16
// baseline (speedup 1.0000x reference)
#include <cuda_runtime.h>
#include <stdint.h>

// SortPooling: B graphs, spans (start,end) per graph, n = end-start in [32,96].
// Select top K=30 rows by feature column 127 (descending, stable ascending-index
// tie-break, matching jax.lax.top_k), copy full 128-float rows to out[b][k][:].

#define BD   128    // feature dim D
#define KK   30     // top-k
#define MAXN 96
#define NT   256    // threads per block

__global__ __launch_bounds__(NT, 6)
void sortpool_kernel(const float* __restrict__ feat,
                     const void* __restrict__ gidx_raw,
                     float* __restrict__ out,
                     long long n_total)
{
    const int b   = blockIdx.x;
    const int tid = threadIdx.x;

    // Inline dtype resolution: int64 view of this block's span must give a
    // plausible span (0 <= start <= end, 0 < n <= 128, end <= n_total).
    // An int32 buffer misread as int64 fuses two values -> fails the check.
    const long long* g64 = (const long long*)gidx_raw;
    long long start = g64[2LL * b];
    long long end   = g64[2LL * b + 1];
    {
        long long nn = end - start;
        bool ok64 = (start >= 0) && (nn > 0) && (nn <= 128) && (end <= n_total);
        if (!ok64) {
            const int* g32 = (const int*)gidx_raw;
            start = g32[2 * b];
            end   = g32[2 * b + 1];
        }
    }

    // Defensive clamps: any residual misinterpretation degrades to wrong
    // values (diagnosable rel_err), not an illegal access.
    if (start < 0) start = 0;
    if (start > n_total) start = n_total;
    long long nn = end - start;
    int n = (nn < 0) ? 0 : (nn > MAXN ? MAXN : (int)nn);
    if (start + n > n_total) n = (int)(n_total - start);

    __shared__ float keys[MAXN];
    __shared__ int   src[KK];   // output slot k -> local row index

    // Phase 1: load sort keys (column 127 of each row in the span).
    if (tid < KK) src[tid] = 0;
    if (tid < n) {
        keys[tid] = __ldg(&feat[(start + (long long)tid) * BD + (BD - 1)]);
    }
    __syncthreads();

    // Phase 2: rank selection. rank_j = #{i : key_i > key_j or
    // (key_i == key_j and i < tid)} — descending value, stable index
    // tie-break, exactly jax.lax.top_k ordering. Ranks are a permutation
    // of 0..n-1; since n >= 32 > K, slots 0..K-1 are all filled.
    if (tid < n) {
        const float kj = keys[tid];
        int rank = 0;
        #pragma unroll 4
        for (int i = 0; i < n; ++i) {
            const float ki = keys[i];
            rank += (ki > kj) || (ki == kj && i < tid);
        }
        if (rank < KK) src[rank] = tid;
    }
    __syncthreads();

    // Phase 3: gather K rows of 128 floats -> 30 * 32 = 960 float4 moves.
    // Each warp moves one full 512B row per iteration (coalesced both sides).
    // Streaming hints: output is write-once (__stcs), gathered rows are
    // read-once (__ldcs) — keep them from churning L2.
    float4* __restrict__ dst = (float4*)(out + (size_t)b * (KK * BD));
    const int total = KK * (BD / 4);   // 960
    #pragma unroll 4
    for (int t = tid; t < total; t += NT) {
        const int k = t >> 5;          // which of the K rows
        const int c = t & 31;          // which float4 within the row
        long long row = start + (long long)src[k];
        if (row >= n_total) row = n_total - 1;   // defensive
        float4 v = __ldcs(((const float4*)(feat + row * BD)) + c);
        __stcs(dst + t, v);
    }
}

extern "C" void kernel_launch(void* const* d_in, const int* in_sizes, int n_in,
                              void* d_out, int out_size)
{
    // Pick inputs by element count: features is huge (~67M), spans are tiny.
    int i_feat = 0, i_gidx = 1;
    if (n_in >= 2 && in_sizes[0] < in_sizes[1]) { i_feat = 1; i_gidx = 0; }

    const float* feat = (const float*)d_in[i_feat];
    const void*  gidx = d_in[i_gidx];
    float*       out  = (float*)d_out;

    const long long n_total = (long long)in_sizes[i_feat] / BD;
    const int       B       = in_sizes[i_gidx] / 2;

    sortpool_kernel<<<B, NT>>>(feat, gidx, out, n_total);
}

// round 17
// speedup vs baseline: 1.1728x; 1.1728x over previous
#include <cuda_runtime.h>
#include <stdint.h>

// SortPooling: B graphs, spans (start,end) per graph, n = end-start in [32,96].
// Select top K=30 rows by feature column 127 (descending, stable ascending-index
// tie-break, matching jax.lax.top_k), copy full 128-float rows to out[b][k][:].

#define BD   128    // feature dim D
#define KK   30     // top-k
#define MAXN 96
#define NT   128    // threads per block

__global__ __launch_bounds__(NT, 8)
void sortpool_kernel(const float* __restrict__ feat,
                     const void* __restrict__ gidx_raw,
                     float* __restrict__ out,
                     long long n_total)
{
    const int b   = blockIdx.x;
    const int tid = threadIdx.x;

    // Inline dtype resolution: the int64 view of this block's span must give a
    // plausible span (0 <= start <= end <= n_total, 0 < n <= 128). An int32
    // buffer misread as int64 fuses two values -> fails the check.
    const long long* g64 = (const long long*)gidx_raw;
    long long start = g64[2LL * b];
    long long end   = g64[2LL * b + 1];
    {
        long long nn = end - start;
        bool ok64 = (start >= 0) && (nn > 0) && (nn <= 128) && (end <= n_total);
        if (!ok64) {
            const int* g32 = (const int*)gidx_raw;
            start = g32[2 * b];
            end   = g32[2 * b + 1];
        }
    }

    // Defensive clamps: misinterpretation degrades to wrong values, not a crash.
    if (start < 0) start = 0;
    if (start > n_total) start = n_total;
    long long nn = end - start;
    int n = (nn < 0) ? 0 : (nn > MAXN ? MAXN : (int)nn);
    if (start + n > n_total) n = (int)(n_total - start);

    __shared__ float keys[MAXN];
    __shared__ int   src[KK];   // output slot k -> local row index

    // Phase 1: load sort keys (column 127 of each row in the span).
    if (tid < KK) src[tid] = 0;
    if (tid < n) {
        keys[tid] = __ldg(&feat[(start + (long long)tid) * BD + (BD - 1)]);
    }
    __syncthreads();

    // Phase 2: rank selection. rank_j = #{i : key_i > key_j or
    // (key_i == key_j and i < tid)} — descending value, stable index
    // tie-break, exactly jax.lax.top_k ordering. Ranks are a permutation
    // of 0..n-1; since n >= 32 > K, slots 0..K-1 are all filled.
    if (tid < n) {
        const float kj = keys[tid];
        int rank = 0;
        #pragma unroll 4
        for (int i = 0; i < n; ++i) {
            const float ki = keys[i];
            rank += (ki > kj) || (ki == kj && i < tid);
        }
        if (rank < KK) src[rank] = tid;
    }
    __syncthreads();

    // Phase 3: gather K rows of 128 floats = 960 float4 moves, NT=128.
    // Thread layout: element t = tid + i*128 -> k = (tid>>5) + 4*i (row slot),
    // c = tid&31 (constant float4 column per thread). Threads tid<64 own 8
    // elements, tid>=64 own 7. Batch ALL loads first (MLP=8 per thread, fully
    // coalesced 512B per warp per step), then all stores.
    float4* __restrict__ dst = (float4*)(out + (size_t)b * (KK * BD));
    const int c  = tid & 31;
    const int k0 = tid >> 5;
    const bool full = (tid < 64);          // has the 8th element (k0+28 < 30)

    float4 v[8];
    #pragma unroll
    for (int i = 0; i < 7; ++i) {
        long long row = start + (long long)src[k0 + 4 * i];
        if (row >= n_total) row = n_total - 1;   // defensive
        v[i] = __ldg(((const float4*)(feat + row * BD)) + c);
    }
    if (full) {
        long long row = start + (long long)src[k0 + 28];
        if (row >= n_total) row = n_total - 1;   // defensive
        v[7] = __ldg(((const float4*)(feat + row * BD)) + c);
    }

    #pragma unroll
    for (int i = 0; i < 7; ++i) {
        dst[tid + i * NT] = v[i];
    }
    if (full) {
        dst[tid + 7 * NT] = v[7];
    }
}

extern "C" void kernel_launch(void* const* d_in, const int* in_sizes, int n_in,
                              void* d_out, int out_size)
{
    // Pick inputs by element count: features is huge (~67M), spans are tiny.
    int i_feat = 0, i_gidx = 1;
    if (n_in >= 2 && in_sizes[0] < in_sizes[1]) { i_feat = 1; i_gidx = 0; }

    const float* feat = (const float*)d_in[i_feat];
    const void*  gidx = d_in[i_gidx];
    float*       out  = (float*)d_out;

    const long long n_total = (long long)in_sizes[i_feat] / BD;
    const int       B       = in_sizes[i_gidx] / 2;

    sortpool_kernel<<<B, NT>>>(feat, gidx, out, n_total);
}